// round 4
// baseline (speedup 1.0000x reference)
#include <cuda_runtime.h>

#define B 8
#define T 1024
#define E 128
#define H 8
#define S 16
#define BH (B*H)

// ---- scratch (device globals; no allocation allowed) ----
__device__ float g_Qc[BH*T*S];     // compacted, scaled Q  [b][h][rank][s]
__device__ float g_Kc[BH*T*S];     // compacted, scaled K
__device__ float g_Vc[BH*T*S];     // compacted V
__device__ float g_AttnO[B*T*E];   // attention output (pre-projection)
__device__ float g_WuT[E*E];       // Wu transposed: WuT[i][j] = Wu[j][i]
__device__ int   g_idx[B*T];       // compacted j -> original t
__device__ int   g_rank[B*T];      // original t -> compacted j (or -1)
__device__ int   g_cnt[B];         // unmasked count per batch

// ------------------------------------------------------------------
// 1. Order-preserving compaction of unmasked positions (per batch)
// ------------------------------------------------------------------
__global__ void compact_kernel(const int* __restrict__ masks) {
    int b = blockIdx.x;
    int t = threadIdx.x;            // 1024 threads
    int v = (masks[b*T + t] != 0) ? 1 : 0;
    unsigned bal = __ballot_sync(0xffffffffu, v);
    int lane = t & 31, warp = t >> 5;
    int wprefix = __popc(bal & ((1u << lane) - 1u));
    __shared__ int wcnt[32];
    __shared__ int wbase[32];
    if (lane == 31) wcnt[warp] = wprefix + v;
    __syncthreads();
    if (t == 0) {
        int acc = 0;
        for (int w = 0; w < 32; w++) { wbase[w] = acc; acc += wcnt[w]; }
        g_cnt[b] = acc;
    }
    __syncthreads();
    int r = v ? (wbase[warp] + wprefix) : -1;
    g_rank[b*T + t] = r;
    if (v) g_idx[b*T + r] = t;
}

// ------------------------------------------------------------------
// 2. Transpose Wu (tiny)
// ------------------------------------------------------------------
__global__ void transpose_wu(const float* __restrict__ Wu) {
    int i = blockIdx.x * 256 + threadIdx.x;   // 64 blocks * 256 = 16384
    int r = i >> 7, c = i & 127;
    g_WuT[i] = Wu[c*E + r];
}

// ------------------------------------------------------------------
// 3. QKV projection per (b,t,h), compacted scatter; zero masked rows
// ------------------------------------------------------------------
__global__ __launch_bounds__(256) void qkv_kernel(
    const float* __restrict__ x, const int* __restrict__ masks,
    const float* __restrict__ Wq, const float* __restrict__ Wk,
    const float* __restrict__ Wv)
{
    __shared__ float sW[3][S*S];
    int tid = threadIdx.x;          // 256 = S*S
    sW[0][tid] = Wq[tid];
    sW[1][tid] = Wk[tid];
    sW[2][tid] = Wv[tid];
    __syncthreads();

    int gid = blockIdx.x * 256 + tid;   // (b*T + t)*H + h
    int h  = gid & 7;
    int bt = gid >> 3;
    int msk = masks[bt];
    if (!msk) {
        float4 z = make_float4(0.f, 0.f, 0.f, 0.f);
        float4* op = (float4*)(g_AttnO + bt*E + h*S);
        op[0] = z; op[1] = z; op[2] = z; op[3] = z;
        return;
    }
    float xr[S];
    const float4* xp = (const float4*)(x + bt*E + h*S);
#pragma unroll
    for (int i = 0; i < 4; i++) {
        float4 v = xp[i];
        xr[4*i] = v.x; xr[4*i+1] = v.y; xr[4*i+2] = v.z; xr[4*i+3] = v.w;
    }
    int r = g_rank[bt];
    int b = bt >> 10;
    int base = ((b*H + h)*T + r)*S;
    const float invs = 0.29730177875068026f;   // 128^-0.25

    float o[S];
    // Q
#pragma unroll
    for (int d = 0; d < S; d++) {
        float a = 0.f;
#pragma unroll
        for (int s2 = 0; s2 < S; s2++) a = fmaf(sW[0][d*S + s2], xr[s2], a);
        o[d] = a * invs;
    }
    {
        float4* qp = (float4*)(g_Qc + base);
#pragma unroll
        for (int i = 0; i < 4; i++) qp[i] = make_float4(o[4*i], o[4*i+1], o[4*i+2], o[4*i+3]);
    }
    // K
#pragma unroll
    for (int d = 0; d < S; d++) {
        float a = 0.f;
#pragma unroll
        for (int s2 = 0; s2 < S; s2++) a = fmaf(sW[1][d*S + s2], xr[s2], a);
        o[d] = a * invs;
    }
    {
        float4* kp = (float4*)(g_Kc + base);
#pragma unroll
        for (int i = 0; i < 4; i++) kp[i] = make_float4(o[4*i], o[4*i+1], o[4*i+2], o[4*i+3]);
    }
    // V
#pragma unroll
    for (int d = 0; d < S; d++) {
        float a = 0.f;
#pragma unroll
        for (int s2 = 0; s2 < S; s2++) a = fmaf(sW[2][d*S + s2], xr[s2], a);
        o[d] = a;
    }
    {
        float4* vp = (float4*)(g_Vc + base);
#pragma unroll
        for (int i = 0; i < 4; i++) vp[i] = make_float4(o[4*i], o[4*i+1], o[4*i+2], o[4*i+3]);
    }
}

// ------------------------------------------------------------------
// 4. Flash-style attention over compacted sequences
// ------------------------------------------------------------------
#define ATH   64      // threads per block
#define QPT   2       // queries per thread
#define QBLK  (ATH*QPT)   // 128 queries per block
#define KTILE 128

__global__ __launch_bounds__(ATH) void attn_kernel() {
    __shared__ float4 sK[KTILE][5];   // [5] pad: conflict-free float4 stores
    __shared__ float4 sV[KTILE][5];

    int bh = blockIdx.y;
    int b  = bh >> 3;
    int cnt = g_cnt[b];
    if ((int)(blockIdx.x * QBLK) >= cnt) return;
    int tid = threadIdx.x;

    const float* Qb = g_Qc + bh*T*S;
    const float* Kb = g_Kc + bh*T*S;
    const float* Vb = g_Vc + bh*T*S;

    int   jj[QPT];
    float q[QPT][S], o[QPT][S], mx[QPT], l[QPT];
#pragma unroll
    for (int p = 0; p < QPT; p++) {
        jj[p] = blockIdx.x*QBLK + tid + p*ATH;
        const float4* qp = (const float4*)(Qb + jj[p]*S);
#pragma unroll
        for (int i = 0; i < 4; i++) {
            float4 v = qp[i];
            q[p][4*i] = v.x; q[p][4*i+1] = v.y; q[p][4*i+2] = v.z; q[p][4*i+3] = v.w;
        }
        mx[p] = -1e30f; l[p] = 0.f;
#pragma unroll
        for (int d = 0; d < S; d++) o[p][d] = 0.f;
    }

    for (int kt = 0; kt < cnt; kt += KTILE) {
        int nk = min(KTILE, cnt - kt);
        __syncthreads();
        for (int rr = tid; rr < nk; rr += ATH) {
            const float4* kp = (const float4*)(Kb + (kt+rr)*S);
            const float4* vp = (const float4*)(Vb + (kt+rr)*S);
#pragma unroll
            for (int c = 0; c < 4; c++) { sK[rr][c] = kp[c]; sV[rr][c] = vp[c]; }
        }
        __syncthreads();
        for (int kk = 0; kk < nk; kk++) {
            float4 k0 = sK[kk][0], k1 = sK[kk][1], k2 = sK[kk][2], k3 = sK[kk][3];
            float4 v0 = sV[kk][0], v1 = sV[kk][1], v2 = sV[kk][2], v3 = sV[kk][3];
#pragma unroll
            for (int p = 0; p < QPT; p++) {
                const float* qp = q[p];
                float a0 = fmaf(qp[3],  k0.w, fmaf(qp[2],  k0.z, fmaf(qp[1],  k0.y, qp[0]  * k0.x)));
                float a1 = fmaf(qp[7],  k1.w, fmaf(qp[6],  k1.z, fmaf(qp[5],  k1.y, qp[4]  * k1.x)));
                float a2 = fmaf(qp[11], k2.w, fmaf(qp[10], k2.z, fmaf(qp[9],  k2.y, qp[8]  * k2.x)));
                float a3 = fmaf(qp[15], k3.w, fmaf(qp[14], k3.z, fmaf(qp[13], k3.y, qp[12] * k3.x)));
                float s = (a0 + a1) + (a2 + a3);
                if (s > mx[p]) {
                    float al = __expf(mx[p] - s);
                    mx[p] = s;
                    l[p] *= al;
#pragma unroll
                    for (int d = 0; d < S; d++) o[p][d] *= al;
                }
                float w = __expf(s - mx[p]);
                l[p] += w;
                float* op = o[p];
                op[0]  = fmaf(w, v0.x, op[0]);  op[1]  = fmaf(w, v0.y, op[1]);
                op[2]  = fmaf(w, v0.z, op[2]);  op[3]  = fmaf(w, v0.w, op[3]);
                op[4]  = fmaf(w, v1.x, op[4]);  op[5]  = fmaf(w, v1.y, op[5]);
                op[6]  = fmaf(w, v1.z, op[6]);  op[7]  = fmaf(w, v1.w, op[7]);
                op[8]  = fmaf(w, v2.x, op[8]);  op[9]  = fmaf(w, v2.y, op[9]);
                op[10] = fmaf(w, v2.z, op[10]); op[11] = fmaf(w, v2.w, op[11]);
                op[12] = fmaf(w, v3.x, op[12]); op[13] = fmaf(w, v3.y, op[13]);
                op[14] = fmaf(w, v3.z, op[14]); op[15] = fmaf(w, v3.w, op[15]);
            }
        }
    }

#pragma unroll
    for (int p = 0; p < QPT; p++) {
        if (jj[p] < cnt) {
            int t = g_idx[b*T + jj[p]];
            float invl = (l[p] > 0.f) ? (1.0f / l[p]) : 0.f;
            float4* outp = (float4*)(g_AttnO + (b*T + t)*E + (bh & 7)*S);
#pragma unroll
            for (int i = 0; i < 4; i++)
                outp[i] = make_float4(o[p][4*i]*invl, o[p][4*i+1]*invl,
                                      o[p][4*i+2]*invl, o[p][4*i+3]*invl);
        }
    }
}

// ------------------------------------------------------------------
// 5. Output projection: out = AttnO @ Wu^T + bu
// ------------------------------------------------------------------
#define PR 16
__global__ __launch_bounds__(512) void proj_kernel(const float* __restrict__ bu,
                                                   float* __restrict__ out) {
    __shared__ float xs[PR][E];
    int tid = threadIdx.x;        // 512
    int rowbase = blockIdx.x * PR;
    const float* src = g_AttnO + rowbase*E;
    for (int i = tid; i < PR*E; i += 512) xs[i >> 7][i & 127] = src[i];
    __syncthreads();

    int row = tid >> 5;           // 0..15 (uniform per warp -> smem broadcast)
    int cg  = (tid & 31) * 4;     // column group
    float ax = 0.f, ay = 0.f, az = 0.f, aw = 0.f;
#pragma unroll 8
    for (int i = 0; i < E; i++) {
        float xv = xs[row][i];
        float4 w = *(const float4*)(g_WuT + i*E + cg);
        ax = fmaf(xv, w.x, ax); ay = fmaf(xv, w.y, ay);
        az = fmaf(xv, w.z, az); aw = fmaf(xv, w.w, aw);
    }
    float4 bb = *(const float4*)(bu + cg);
    *(float4*)(out + (rowbase + row)*E + cg) =
        make_float4(ax + bb.x, ay + bb.y, az + bb.z, aw + bb.w);
}

// ------------------------------------------------------------------
extern "C" void kernel_launch(void* const* d_in, const int* in_sizes, int n_in,
                              void* d_out, int out_size) {
    const float* x     = (const float*)d_in[0];
    const int*   masks = (const int*)  d_in[1];
    const float* Wq    = (const float*)d_in[2];
    const float* Wk    = (const float*)d_in[3];
    const float* Wv    = (const float*)d_in[4];
    const float* Wu    = (const float*)d_in[5];
    const float* bu    = (const float*)d_in[6];
    float* out = (float*)d_out;

    compact_kernel<<<B, 1024>>>(masks);
    transpose_wu<<<64, 256>>>(Wu);
    qkv_kernel<<<(B*T*H)/256, 256>>>(x, masks, Wq, Wk, Wv);
    attn_kernel<<<dim3(T/QBLK, BH), ATH>>>();
    proj_kernel<<<(B*T)/PR, 512>>>(bu, out);
}

// round 5
// speedup vs baseline: 1.2481x; 1.2481x over previous
#include <cuda_runtime.h>

#define B 8
#define T 1024
#define E 128
#define H 8
#define S 16
#define BH (B*H)
#define KSPLIT 4

// ---- scratch (device globals; no allocation allowed) ----
__device__ float g_Qc[BH*T*S];     // compacted, scaled Q  [b][h][rank][s]
__device__ float g_Kc[BH*T*S];     // compacted, scaled K
__device__ float g_Vc[BH*T*S];     // compacted V
__device__ float g_AttnO[B*T*E];   // attention output (pre-projection)
__device__ float g_WuT[E*E];       // Wu transposed
__device__ int   g_idx[B*T];       // compacted j -> original t
__device__ int   g_rank[B*T];      // original t -> compacted j (or -1)
__device__ int   g_cnt[B];         // unmasked count per batch
// split-K partials
__device__ float g_pM[KSPLIT*BH*T];
__device__ float g_pL[KSPLIT*BH*T];
__device__ float g_pO[KSPLIT*BH*T*S];

// ------------------------------------------------------------------
// 1. Order-preserving compaction of unmasked positions (per batch)
// ------------------------------------------------------------------
__global__ void compact_kernel(const int* __restrict__ masks) {
    int b = blockIdx.x;
    int t = threadIdx.x;            // 1024 threads
    int v = (masks[b*T + t] != 0) ? 1 : 0;
    unsigned bal = __ballot_sync(0xffffffffu, v);
    int lane = t & 31, warp = t >> 5;
    int wprefix = __popc(bal & ((1u << lane) - 1u));
    __shared__ int wcnt[32];
    __shared__ int wbase[32];
    if (lane == 31) wcnt[warp] = wprefix + v;
    __syncthreads();
    if (t == 0) {
        int acc = 0;
        for (int w = 0; w < 32; w++) { wbase[w] = acc; acc += wcnt[w]; }
        g_cnt[b] = acc;
    }
    __syncthreads();
    int r = v ? (wbase[warp] + wprefix) : -1;
    g_rank[b*T + t] = r;
    if (v) g_idx[b*T + r] = t;
}

// ------------------------------------------------------------------
// 2. Transpose Wu (tiny)
// ------------------------------------------------------------------
__global__ void transpose_wu(const float* __restrict__ Wu) {
    int i = blockIdx.x * 256 + threadIdx.x;
    int r = i >> 7, c = i & 127;
    g_WuT[i] = Wu[c*E + r];
}

// ------------------------------------------------------------------
// 3. QKV projection per (b,t,h), compacted scatter; zero masked rows
// ------------------------------------------------------------------
__global__ __launch_bounds__(256) void qkv_kernel(
    const float* __restrict__ x, const int* __restrict__ masks,
    const float* __restrict__ Wq, const float* __restrict__ Wk,
    const float* __restrict__ Wv)
{
    __shared__ float sW[3][S*S];
    int tid = threadIdx.x;          // 256 = S*S
    sW[0][tid] = Wq[tid];
    sW[1][tid] = Wk[tid];
    sW[2][tid] = Wv[tid];
    __syncthreads();

    int gid = blockIdx.x * 256 + tid;   // (b*T + t)*H + h
    int h  = gid & 7;
    int bt = gid >> 3;
    int msk = masks[bt];
    if (!msk) {
        float4 z = make_float4(0.f, 0.f, 0.f, 0.f);
        float4* op = (float4*)(g_AttnO + bt*E + h*S);
        op[0] = z; op[1] = z; op[2] = z; op[3] = z;
        return;
    }
    float xr[S];
    const float4* xp = (const float4*)(x + bt*E + h*S);
#pragma unroll
    for (int i = 0; i < 4; i++) {
        float4 v = xp[i];
        xr[4*i] = v.x; xr[4*i+1] = v.y; xr[4*i+2] = v.z; xr[4*i+3] = v.w;
    }
    int r = g_rank[bt];
    int b = bt >> 10;
    int base = ((b*H + h)*T + r)*S;
    const float invs = 0.29730177875068026f;   // 128^-0.25

    float o[S];
    // Q
#pragma unroll
    for (int d = 0; d < S; d++) {
        float a = 0.f;
#pragma unroll
        for (int s2 = 0; s2 < S; s2++) a = fmaf(sW[0][d*S + s2], xr[s2], a);
        o[d] = a * invs;
    }
    {
        float4* qp = (float4*)(g_Qc + base);
#pragma unroll
        for (int i = 0; i < 4; i++) qp[i] = make_float4(o[4*i], o[4*i+1], o[4*i+2], o[4*i+3]);
    }
    // K
#pragma unroll
    for (int d = 0; d < S; d++) {
        float a = 0.f;
#pragma unroll
        for (int s2 = 0; s2 < S; s2++) a = fmaf(sW[1][d*S + s2], xr[s2], a);
        o[d] = a * invs;
    }
    {
        float4* kp = (float4*)(g_Kc + base);
#pragma unroll
        for (int i = 0; i < 4; i++) kp[i] = make_float4(o[4*i], o[4*i+1], o[4*i+2], o[4*i+3]);
    }
    // V
#pragma unroll
    for (int d = 0; d < S; d++) {
        float a = 0.f;
#pragma unroll
        for (int s2 = 0; s2 < S; s2++) a = fmaf(sW[2][d*S + s2], xr[s2], a);
        o[d] = a;
    }
    {
        float4* vp = (float4*)(g_Vc + base);
#pragma unroll
        for (int i = 0; i < 4; i++) vp[i] = make_float4(o[4*i], o[4*i+1], o[4*i+2], o[4*i+3]);
    }
}

// ------------------------------------------------------------------
// 4. Flash-style attention, split along the key axis (KSPLIT chunks)
// ------------------------------------------------------------------
#define ATH   64      // threads per block
#define QPT   2       // queries per thread
#define QBLK  (ATH*QPT)   // 128 queries per block
#define KTILE 128

__global__ __launch_bounds__(ATH) void attn_split_kernel() {
    __shared__ float4 sK[KTILE][5];   // [5] pad: conflict-free float4 stores
    __shared__ float4 sV[KTILE][5];

    int bh = blockIdx.y;
    int ks = blockIdx.z;
    int b  = bh >> 3;
    int cnt = g_cnt[b];
    if ((int)(blockIdx.x * QBLK) >= cnt) return;
    int k0 = (ks * cnt) / KSPLIT;
    int k1 = ((ks + 1) * cnt) / KSPLIT;
    int tid = threadIdx.x;

    const float* Qb = g_Qc + bh*T*S;
    const float* Kb = g_Kc + bh*T*S;
    const float* Vb = g_Vc + bh*T*S;

    int   jj[QPT];
    float q[QPT][S], o[QPT][S], mx[QPT], l[QPT];
#pragma unroll
    for (int p = 0; p < QPT; p++) {
        jj[p] = blockIdx.x*QBLK + tid + p*ATH;
        const float4* qp = (const float4*)(Qb + jj[p]*S);
#pragma unroll
        for (int i = 0; i < 4; i++) {
            float4 v = qp[i];
            q[p][4*i] = v.x; q[p][4*i+1] = v.y; q[p][4*i+2] = v.z; q[p][4*i+3] = v.w;
        }
        mx[p] = -1e30f; l[p] = 0.f;
#pragma unroll
        for (int d = 0; d < S; d++) o[p][d] = 0.f;
    }

    for (int kt = k0; kt < k1; kt += KTILE) {
        int nk = min(KTILE, k1 - kt);
        __syncthreads();
        for (int rr = tid; rr < nk; rr += ATH) {
            const float4* kp = (const float4*)(Kb + (kt+rr)*S);
            const float4* vp = (const float4*)(Vb + (kt+rr)*S);
#pragma unroll
            for (int c = 0; c < 4; c++) { sK[rr][c] = kp[c]; sV[rr][c] = vp[c]; }
        }
        __syncthreads();
        for (int kk = 0; kk < nk; kk++) {
            float4 k0v = sK[kk][0], k1v = sK[kk][1], k2v = sK[kk][2], k3v = sK[kk][3];
            float4 v0 = sV[kk][0], v1 = sV[kk][1], v2 = sV[kk][2], v3 = sV[kk][3];
#pragma unroll
            for (int p = 0; p < QPT; p++) {
                const float* qp = q[p];
                float a0 = fmaf(qp[3],  k0v.w, fmaf(qp[2],  k0v.z, fmaf(qp[1],  k0v.y, qp[0]  * k0v.x)));
                float a1 = fmaf(qp[7],  k1v.w, fmaf(qp[6],  k1v.z, fmaf(qp[5],  k1v.y, qp[4]  * k1v.x)));
                float a2 = fmaf(qp[11], k2v.w, fmaf(qp[10], k2v.z, fmaf(qp[9],  k2v.y, qp[8]  * k2v.x)));
                float a3 = fmaf(qp[15], k3v.w, fmaf(qp[14], k3v.z, fmaf(qp[13], k3v.y, qp[12] * k3v.x)));
                float s = (a0 + a1) + (a2 + a3);
                if (s > mx[p]) {
                    float al = __expf(mx[p] - s);
                    mx[p] = s;
                    l[p] *= al;
#pragma unroll
                    for (int d = 0; d < S; d++) o[p][d] *= al;
                }
                float w = __expf(s - mx[p]);
                l[p] += w;
                float* op = o[p];
                op[0]  = fmaf(w, v0.x, op[0]);  op[1]  = fmaf(w, v0.y, op[1]);
                op[2]  = fmaf(w, v0.z, op[2]);  op[3]  = fmaf(w, v0.w, op[3]);
                op[4]  = fmaf(w, v1.x, op[4]);  op[5]  = fmaf(w, v1.y, op[5]);
                op[6]  = fmaf(w, v1.z, op[6]);  op[7]  = fmaf(w, v1.w, op[7]);
                op[8]  = fmaf(w, v2.x, op[8]);  op[9]  = fmaf(w, v2.y, op[9]);
                op[10] = fmaf(w, v2.z, op[10]); op[11] = fmaf(w, v2.w, op[11]);
                op[12] = fmaf(w, v3.x, op[12]); op[13] = fmaf(w, v3.y, op[13]);
                op[14] = fmaf(w, v3.z, op[14]); op[15] = fmaf(w, v3.w, op[15]);
            }
        }
    }

    // store unnormalized partials
#pragma unroll
    for (int p = 0; p < QPT; p++) {
        if (jj[p] < cnt) {
            int base = (ks*BH + bh)*T + jj[p];
            g_pM[base] = mx[p];
            g_pL[base] = l[p];
            float4* op = (float4*)(g_pO + base*S);
#pragma unroll
            for (int i = 0; i < 4; i++)
                op[i] = make_float4(o[p][4*i], o[p][4*i+1], o[p][4*i+2], o[p][4*i+3]);
        }
    }
}

// ------------------------------------------------------------------
// 4b. Combine split-K partials -> g_AttnO
// ------------------------------------------------------------------
__global__ __launch_bounds__(256) void attn_combine_kernel() {
    int g = blockIdx.x * 256 + threadIdx.x;   // bh*T + j
    int j  = g & (T-1);
    int bh = g >> 10;
    int b  = bh >> 3;
    if (j >= g_cnt[b]) return;

    float m[KSPLIT], l[KSPLIT];
    float M = -1e30f;
#pragma unroll
    for (int ks = 0; ks < KSPLIT; ks++) {
        int base = (ks*BH + bh)*T + j;
        m[ks] = g_pM[base];
        l[ks] = g_pL[base];
        M = fmaxf(M, m[ks]);
    }
    float L = 0.f;
    float w[KSPLIT];
#pragma unroll
    for (int ks = 0; ks < KSPLIT; ks++) {
        w[ks] = __expf(m[ks] - M);
        L = fmaf(l[ks], w[ks], L);
    }
    float acc[S];
#pragma unroll
    for (int d = 0; d < S; d++) acc[d] = 0.f;
#pragma unroll
    for (int ks = 0; ks < KSPLIT; ks++) {
        const float4* op = (const float4*)(g_pO + ((ks*BH + bh)*T + j)*S);
        float ww = w[ks];
#pragma unroll
        for (int i = 0; i < 4; i++) {
            float4 v = op[i];
            acc[4*i]   = fmaf(ww, v.x, acc[4*i]);
            acc[4*i+1] = fmaf(ww, v.y, acc[4*i+1]);
            acc[4*i+2] = fmaf(ww, v.z, acc[4*i+2]);
            acc[4*i+3] = fmaf(ww, v.w, acc[4*i+3]);
        }
    }
    float invL = (L > 0.f) ? (1.0f / L) : 0.f;
    int t = g_idx[b*T + j];
    float4* outp = (float4*)(g_AttnO + (b*T + t)*E + (bh & 7)*S);
#pragma unroll
    for (int i = 0; i < 4; i++)
        outp[i] = make_float4(acc[4*i]*invL, acc[4*i+1]*invL,
                              acc[4*i+2]*invL, acc[4*i+3]*invL);
}

// ------------------------------------------------------------------
// 5. Output projection: out = AttnO @ Wu^T + bu
// ------------------------------------------------------------------
#define PR 16
__global__ __launch_bounds__(512) void proj_kernel(const float* __restrict__ bu,
                                                   float* __restrict__ out) {
    __shared__ float xs[PR][E];
    int tid = threadIdx.x;        // 512
    int rowbase = blockIdx.x * PR;
    const float* src = g_AttnO + rowbase*E;
    for (int i = tid; i < PR*E; i += 512) xs[i >> 7][i & 127] = src[i];
    __syncthreads();

    int row = tid >> 5;           // 0..15
    int cg  = (tid & 31) * 4;     // column group
    float ax = 0.f, ay = 0.f, az = 0.f, aw = 0.f;
#pragma unroll 8
    for (int i = 0; i < E; i++) {
        float xv = xs[row][i];
        float4 w = *(const float4*)(g_WuT + i*E + cg);
        ax = fmaf(xv, w.x, ax); ay = fmaf(xv, w.y, ay);
        az = fmaf(xv, w.z, az); aw = fmaf(xv, w.w, aw);
    }
    float4 bb = *(const float4*)(bu + cg);
    *(float4*)(out + (rowbase + row)*E + cg) =
        make_float4(ax + bb.x, ay + bb.y, az + bb.z, aw + bb.w);
}

// ------------------------------------------------------------------
extern "C" void kernel_launch(void* const* d_in, const int* in_sizes, int n_in,
                              void* d_out, int out_size) {
    const float* x     = (const float*)d_in[0];
    const int*   masks = (const int*)  d_in[1];
    const float* Wq    = (const float*)d_in[2];
    const float* Wk    = (const float*)d_in[3];
    const float* Wv    = (const float*)d_in[4];
    const float* Wu    = (const float*)d_in[5];
    const float* bu    = (const float*)d_in[6];
    float* out = (float*)d_out;

    compact_kernel<<<B, 1024>>>(masks);
    transpose_wu<<<64, 256>>>(Wu);
    qkv_kernel<<<(B*T*H)/256, 256>>>(x, masks, Wq, Wk, Wv);
    attn_split_kernel<<<dim3(T/QBLK, BH, KSPLIT), ATH>>>();
    attn_combine_kernel<<<(BH*T)/256, 256>>>();
    proj_kernel<<<(B*T)/PR, 512>>>(bu, out);
}

// round 6
// speedup vs baseline: 1.6055x; 1.2864x over previous
#include <cuda_runtime.h>

#define B 8
#define T 1024
#define E 128
#define H 8
#define S 16
#define BH (B*H)
#define KSPLIT 8

// ---- packed f32x2 helpers (sm_103a FFMA2 path, PTX-only) ----
typedef unsigned long long ull;
__device__ __forceinline__ ull ffma2(ull a, ull b, ull c) {
    ull d; asm("fma.rn.f32x2 %0, %1, %2, %3;" : "=l"(d) : "l"(a), "l"(b), "l"(c)); return d;
}
__device__ __forceinline__ ull fmul2(ull a, ull b) {
    ull d; asm("mul.rn.f32x2 %0, %1, %2;" : "=l"(d) : "l"(a), "l"(b)); return d;
}
__device__ __forceinline__ ull fadd2(ull a, ull b) {
    ull d; asm("add.rn.f32x2 %0, %1, %2;" : "=l"(d) : "l"(a), "l"(b)); return d;
}
__device__ __forceinline__ ull pack2(float lo, float hi) {
    ull d; asm("mov.b64 %0, {%1, %2};" : "=l"(d) : "f"(lo), "f"(hi)); return d;
}
__device__ __forceinline__ void unpack2(ull a, float& lo, float& hi) {
    asm("mov.b64 {%0, %1}, %2;" : "=f"(lo), "=f"(hi) : "l"(a));
}

// ---- scratch (device globals; no allocation allowed) ----
__device__ float g_Qc[BH*T*S];     // compacted, scaled Q  [b][h][rank][s]
__device__ float g_Kc[BH*T*S];     // compacted, scaled K
__device__ float g_Vc[BH*T*S];     // compacted V
__device__ float g_AttnO[B*T*E];   // attention output (pre-projection)
__device__ float g_WuT[E*E];       // Wu transposed
__device__ int   g_idx[B*T];       // compacted j -> original t
__device__ int   g_rank[B*T];      // original t -> compacted j (or -1)
__device__ int   g_cnt[B];         // unmasked count per batch
// split-K partials (fixed-base softmax: plain sums, no max bookkeeping)
__device__ float g_pL[KSPLIT*BH*T];
__device__ float g_pO[KSPLIT*BH*T*S];

// ------------------------------------------------------------------
// 1. Order-preserving compaction of unmasked positions (per batch)
// ------------------------------------------------------------------
__global__ void compact_kernel(const int* __restrict__ masks) {
    int b = blockIdx.x;
    int t = threadIdx.x;            // 1024 threads
    int v = (masks[b*T + t] != 0) ? 1 : 0;
    unsigned bal = __ballot_sync(0xffffffffu, v);
    int lane = t & 31, warp = t >> 5;
    int wprefix = __popc(bal & ((1u << lane) - 1u));
    __shared__ int wcnt[32];
    __shared__ int wbase[32];
    if (lane == 31) wcnt[warp] = wprefix + v;
    __syncthreads();
    if (t == 0) {
        int acc = 0;
        for (int w = 0; w < 32; w++) { wbase[w] = acc; acc += wcnt[w]; }
        g_cnt[b] = acc;
    }
    __syncthreads();
    int r = v ? (wbase[warp] + wprefix) : -1;
    g_rank[b*T + t] = r;
    if (v) g_idx[b*T + r] = t;
}

// ------------------------------------------------------------------
// 2. Transpose Wu (tiny)
// ------------------------------------------------------------------
__global__ void transpose_wu(const float* __restrict__ Wu) {
    int i = blockIdx.x * 256 + threadIdx.x;
    int r = i >> 7, c = i & 127;
    g_WuT[i] = Wu[c*E + r];
}

// ------------------------------------------------------------------
// 3. QKV projection per (b,t,h), compacted scatter; zero masked rows
// ------------------------------------------------------------------
__global__ __launch_bounds__(256) void qkv_kernel(
    const float* __restrict__ x, const int* __restrict__ masks,
    const float* __restrict__ Wq, const float* __restrict__ Wk,
    const float* __restrict__ Wv)
{
    __shared__ float sW[3][S*S];
    int tid = threadIdx.x;          // 256 = S*S
    sW[0][tid] = Wq[tid];
    sW[1][tid] = Wk[tid];
    sW[2][tid] = Wv[tid];
    __syncthreads();

    int gid = blockIdx.x * 256 + tid;   // (b*T + t)*H + h
    int h  = gid & 7;
    int bt = gid >> 3;
    int msk = masks[bt];
    if (!msk) {
        float4 z = make_float4(0.f, 0.f, 0.f, 0.f);
        float4* op = (float4*)(g_AttnO + bt*E + h*S);
        op[0] = z; op[1] = z; op[2] = z; op[3] = z;
        return;
    }
    float xr[S];
    const float4* xp = (const float4*)(x + bt*E + h*S);
#pragma unroll
    for (int i = 0; i < 4; i++) {
        float4 v = xp[i];
        xr[4*i] = v.x; xr[4*i+1] = v.y; xr[4*i+2] = v.z; xr[4*i+3] = v.w;
    }
    int r = g_rank[bt];
    int b = bt >> 10;
    int base = ((b*H + h)*T + r)*S;
    const float invs = 0.29730177875068026f;   // 128^-0.25

    float o[S];
    // Q
#pragma unroll
    for (int d = 0; d < S; d++) {
        float a = 0.f;
#pragma unroll
        for (int s2 = 0; s2 < S; s2++) a = fmaf(sW[0][d*S + s2], xr[s2], a);
        o[d] = a * invs;
    }
    {
        float4* qp = (float4*)(g_Qc + base);
#pragma unroll
        for (int i = 0; i < 4; i++) qp[i] = make_float4(o[4*i], o[4*i+1], o[4*i+2], o[4*i+3]);
    }
    // K
#pragma unroll
    for (int d = 0; d < S; d++) {
        float a = 0.f;
#pragma unroll
        for (int s2 = 0; s2 < S; s2++) a = fmaf(sW[1][d*S + s2], xr[s2], a);
        o[d] = a * invs;
    }
    {
        float4* kp = (float4*)(g_Kc + base);
#pragma unroll
        for (int i = 0; i < 4; i++) kp[i] = make_float4(o[4*i], o[4*i+1], o[4*i+2], o[4*i+3]);
    }
    // V
#pragma unroll
    for (int d = 0; d < S; d++) {
        float a = 0.f;
#pragma unroll
        for (int s2 = 0; s2 < S; s2++) a = fmaf(sW[2][d*S + s2], xr[s2], a);
        o[d] = a;
    }
    {
        float4* vp = (float4*)(g_Vc + base);
#pragma unroll
        for (int i = 0; i < 4; i++) vp[i] = make_float4(o[4*i], o[4*i+1], o[4*i+2], o[4*i+3]);
    }
}

// ------------------------------------------------------------------
// 4. Attention, fixed-base softmax, split-K, FFMA2 inner loop
// ------------------------------------------------------------------
#define ATH   64              // threads per block
#define QPT   2               // queries per thread
#define QBLK  (ATH*QPT)       // 128 queries per block
#define KTILE 128

__global__ __launch_bounds__(ATH) void attn_split_kernel() {
    __shared__ float4 sK[KTILE][5];   // [5] pad
    __shared__ float4 sV[KTILE][5];

    int bh = blockIdx.y;
    int ks = blockIdx.z;
    int b  = bh >> 3;
    int cnt = g_cnt[b];
    if ((int)(blockIdx.x * QBLK) >= cnt) return;
    int k0 = (ks * cnt) / KSPLIT;
    int k1 = ((ks + 1) * cnt) / KSPLIT;
    int tid = threadIdx.x;

    const float* Qb = g_Qc + bh*T*S;
    const float* Kb = g_Kc + bh*T*S;
    const float* Vb = g_Vc + bh*T*S;

    int jj[QPT];
    ull qq[QPT][8], oo[QPT][8];
    float l[QPT];
#pragma unroll
    for (int p = 0; p < QPT; p++) {
        jj[p] = blockIdx.x*QBLK + tid + p*ATH;
        const ull* qp = (const ull*)(Qb + jj[p]*S);   // jj[p] < T always
#pragma unroll
        for (int i = 0; i < 8; i++) { qq[p][i] = qp[i]; oo[p][i] = 0ULL; }
        l[p] = 0.f;
    }
    bool active = jj[0] < cnt;   // warp-uniform granularity for tail blocks

    for (int kt = k0; kt < k1; kt += KTILE) {
        int nk = min(KTILE, k1 - kt);
        __syncthreads();
        for (int rr = tid; rr < nk; rr += ATH) {
            const float4* kp = (const float4*)(Kb + (kt+rr)*S);
            const float4* vp = (const float4*)(Vb + (kt+rr)*S);
#pragma unroll
            for (int c = 0; c < 4; c++) { sK[rr][c] = kp[c]; sV[rr][c] = vp[c]; }
        }
        __syncthreads();
        if (active) {
            for (int kk = 0; kk < nk; kk++) {
                const ull* kr = (const ull*)(&sK[kk][0]);
                const ull* vr = (const ull*)(&sV[kk][0]);
                ull kv0 = kr[0], kv1 = kr[1], kv2 = kr[2], kv3 = kr[3];
                ull kv4 = kr[4], kv5 = kr[5], kv6 = kr[6], kv7 = kr[7];
                ull vv0 = vr[0], vv1 = vr[1], vv2 = vr[2], vv3 = vr[3];
                ull vv4 = vr[4], vv5 = vr[5], vv6 = vr[6], vv7 = vr[7];
#pragma unroll
                for (int p = 0; p < QPT; p++) {
                    ull a0 = fmul2(qq[p][0], kv0);
                    ull a1 = fmul2(qq[p][1], kv1);
                    a0 = ffma2(qq[p][2], kv2, a0);
                    a1 = ffma2(qq[p][3], kv3, a1);
                    a0 = ffma2(qq[p][4], kv4, a0);
                    a1 = ffma2(qq[p][5], kv5, a1);
                    a0 = ffma2(qq[p][6], kv6, a0);
                    a1 = ffma2(qq[p][7], kv7, a1);
                    a0 = fadd2(a0, a1);
                    float lo, hi; unpack2(a0, lo, hi);
                    float w = __expf(lo + hi);
                    l[p] += w;
                    ull wp = pack2(w, w);
                    oo[p][0] = ffma2(wp, vv0, oo[p][0]);
                    oo[p][1] = ffma2(wp, vv1, oo[p][1]);
                    oo[p][2] = ffma2(wp, vv2, oo[p][2]);
                    oo[p][3] = ffma2(wp, vv3, oo[p][3]);
                    oo[p][4] = ffma2(wp, vv4, oo[p][4]);
                    oo[p][5] = ffma2(wp, vv5, oo[p][5]);
                    oo[p][6] = ffma2(wp, vv6, oo[p][6]);
                    oo[p][7] = ffma2(wp, vv7, oo[p][7]);
                }
            }
        }
    }

    // store unnormalized partial sums
#pragma unroll
    for (int p = 0; p < QPT; p++) {
        if (jj[p] < cnt) {
            int base = (ks*BH + bh)*T + jj[p];
            g_pL[base] = l[p];
            ull* op = (ull*)(g_pO + base*S);
#pragma unroll
            for (int i = 0; i < 8; i++) op[i] = oo[p][i];
        }
    }
}

// ------------------------------------------------------------------
// 4b. Combine split-K partials -> g_AttnO (plain sums + normalize)
// ------------------------------------------------------------------
__global__ __launch_bounds__(256) void attn_combine_kernel() {
    int g = blockIdx.x * 256 + threadIdx.x;   // bh*T + j
    int j  = g & (T-1);
    int bh = g >> 10;
    int b  = bh >> 3;
    if (j >= g_cnt[b]) return;

    float L = 0.f;
    ull acc[8];
#pragma unroll
    for (int i = 0; i < 8; i++) acc[i] = 0ULL;
#pragma unroll
    for (int ks = 0; ks < KSPLIT; ks++) {
        int base = (ks*BH + bh)*T + j;
        L += g_pL[base];
        const ull* op = (const ull*)(g_pO + base*S);
#pragma unroll
        for (int i = 0; i < 8; i++) acc[i] = fadd2(acc[i], op[i]);
    }
    float invL = (L > 0.f) ? (1.0f / L) : 0.f;
    ull il2 = pack2(invL, invL);
    int t = g_idx[b*T + j];
    ull* outp = (ull*)(g_AttnO + (b*T + t)*E + (bh & 7)*S);
#pragma unroll
    for (int i = 0; i < 8; i++) outp[i] = fmul2(acc[i], il2);
}

// ------------------------------------------------------------------
// 5. Output projection: out = AttnO @ Wu^T + bu
// ------------------------------------------------------------------
#define PR 16
__global__ __launch_bounds__(512) void proj_kernel(const float* __restrict__ bu,
                                                   float* __restrict__ out) {
    __shared__ float xs[PR][E];
    int tid = threadIdx.x;        // 512
    int rowbase = blockIdx.x * PR;
    const float* src = g_AttnO + rowbase*E;
    for (int i = tid; i < PR*E; i += 512) xs[i >> 7][i & 127] = src[i];
    __syncthreads();

    int row = tid >> 5;           // 0..15
    int cg  = (tid & 31) * 4;     // column group
    float ax = 0.f, ay = 0.f, az = 0.f, aw = 0.f;
#pragma unroll 8
    for (int i = 0; i < E; i++) {
        float xv = xs[row][i];
        float4 w = *(const float4*)(g_WuT + i*E + cg);
        ax = fmaf(xv, w.x, ax); ay = fmaf(xv, w.y, ay);
        az = fmaf(xv, w.z, az); aw = fmaf(xv, w.w, aw);
    }
    float4 bb = *(const float4*)(bu + cg);
    *(float4*)(out + (rowbase + row)*E + cg) =
        make_float4(ax + bb.x, ay + bb.y, az + bb.z, aw + bb.w);
}

// ------------------------------------------------------------------
extern "C" void kernel_launch(void* const* d_in, const int* in_sizes, int n_in,
                              void* d_out, int out_size) {
    const float* x     = (const float*)d_in[0];
    const int*   masks = (const int*)  d_in[1];
    const float* Wq    = (const float*)d_in[2];
    const float* Wk    = (const float*)d_in[3];
    const float* Wv    = (const float*)d_in[4];
    const float* Wu    = (const float*)d_in[5];
    const float* bu    = (const float*)d_in[6];
    float* out = (float*)d_out;

    compact_kernel<<<B, 1024>>>(masks);
    transpose_wu<<<64, 256>>>(Wu);
    qkv_kernel<<<(B*T*H)/256, 256>>>(x, masks, Wq, Wk, Wv);
    attn_split_kernel<<<dim3(T/QBLK, BH, KSPLIT), ATH>>>();
    attn_combine_kernel<<<(BH*T)/256, 256>>>();
    proj_kernel<<<(B*T)/PR, 512>>>(bu, out);
}